// round 6
// baseline (speedup 1.0000x reference)
#include <cuda_runtime.h>
#include <cstdint>

#define NB  4
#define NTQ 512
#define NTK 512
#define NE  128
#define NF  256   // TWO_E

// Scratch (no allocations allowed)
__device__ float g_qproj[NB * NTQ * NE];               // 1 MB
__device__ float g_kproj[NB * NTK * NE];               // 1 MB
__device__ float g_p[(size_t)NB * NTK * NTQ];          // 4 MB (unnormalized exp)
__device__ float g_zr[NB * NTK];                       // 1/rowsum per (b,t)

__device__ __forceinline__ float tanh_fast(float x) {
    float y;
    asm("tanh.approx.f32 %0, %1;" : "=f"(y) : "f"(x));
    return y;
}

// ---- packed fp32x2 helpers (FFMA2/FMUL2; bit-exact IEEE fp32 per lane) ----
__device__ __forceinline__ unsigned long long pack2(float x, float y) {
    unsigned long long r;
    asm("mov.b64 %0, {%1, %2};" : "=l"(r) : "f"(x), "f"(y));
    return r;
}
__device__ __forceinline__ void ffma2(unsigned long long& d,
                                      unsigned long long a, unsigned long long b) {
    asm("fma.rn.f32x2 %0, %1, %2, %0;" : "+l"(d) : "l"(a), "l"(b));
}
__device__ __forceinline__ unsigned long long mul2(unsigned long long a,
                                                   unsigned long long b) {
    unsigned long long r;
    asm("mul.rn.f32x2 %0, %1, %2;" : "=l"(r) : "l"(a), "l"(b));
    return r;
}
__device__ __forceinline__ float2 unpack2(unsigned long long v) {
    float2 f;
    asm("mov.b64 {%0, %1}, %2;" : "=f"(f.x), "=f"(f.y) : "l"(v));
    return f;
}

// ---- cp.async helpers ----
__device__ __forceinline__ uint32_t smem_u32(const void* p) {
    return (uint32_t)__cvta_generic_to_shared(p);
}
__device__ __forceinline__ void cp16(uint32_t dst, const void* src) {
    asm volatile("cp.async.ca.shared.global [%0], [%1], 16;"
                 :: "r"(dst), "l"(src) : "memory");
}
__device__ __forceinline__ void cp_commit() {
    asm volatile("cp.async.commit_group;" ::: "memory");
}
template <int N>
__device__ __forceinline__ void cp_wait() {
    asm volatile("cp.async.wait_group %0;" :: "n"(N) : "memory");
}

// ---------------------------------------------------------------------------
// Kernel A: projections.  C[r,e] = sum_f A[r,f] * W[f,e]
// A: [2048 x 256], W: [256 x 128].  blockIdx.y selects (query,W1) / (key,W2).
// Tile 16x128, stage K=32, 128 threads, 4x4 micro-tile, f32x2 math.
// cp.async double-buffered: loads never touch registers, can't be sunk.
// A kept [m][k] (no transpose); A reads are warp-broadcast LDS.128 per 4k.
// ---------------------------------------------------------------------------
__global__ __launch_bounds__(128) void proj_kernel(
    const float* __restrict__ query, const float* __restrict__ key,
    const float* __restrict__ W1, const float* __restrict__ W2)
{
    const float* A; const float* W; float* C;
    if (blockIdx.y == 0) { A = query; W = W1; C = g_qproj; }
    else                 { A = key;   W = W2; C = g_kproj; }

    __shared__ float As[2][16][32];    // [buf][m][k]  2KB/buf
    __shared__ float Bs[2][32][128];   // [buf][k][n] 16KB/buf

    const int tid = threadIdx.x;
    const int tx = tid & 31;           // 32 threads over N (x4 cols)
    const int ty = tid >> 5;           // 4 threads over M  (x4 rows)
    const int row0 = blockIdx.x * 16;

    // cp.async chunk mapping (16B chunks)
    const int a_r  = tid >> 3;             // A: 1 chunk/thread
    const int a_c  = (tid & 7) << 2;
    const float* a_src = A + (size_t)(row0 + a_r) * NF + a_c;

    auto issue_stage = [&](int kk, int buf) {
        cp16(smem_u32(&As[buf][a_r][a_c]), a_src + kk);
        #pragma unroll
        for (int i = 0; i < 8; i++) {      // B: 8 chunks/thread
            int c  = tid + (i << 7);
            int k  = c >> 5;
            int n4 = (c & 31) << 2;
            cp16(smem_u32(&Bs[buf][k][n4]), W + (size_t)(kk + k) * NE + n4);
        }
        cp_commit();
    };

    issue_stage(0, 0);

    unsigned long long acc2[4][2];
    #pragma unroll
    for (int i = 0; i < 4; i++) { acc2[i][0] = 0ULL; acc2[i][1] = 0ULL; }

    for (int it = 0; it < 8; it++) {
        const int buf = it & 1;
        if (it < 7) { issue_stage((it + 1) << 5, buf ^ 1); cp_wait<1>(); }
        else        { cp_wait<0>(); }
        __syncthreads();

        #pragma unroll
        for (int k4 = 0; k4 < 32; k4 += 4) {
            float a[4][4];
            #pragma unroll
            for (int i = 0; i < 4; i++) {
                float4 av = *(const float4*)&As[buf][(ty << 2) + i][k4];  // broadcast
                a[i][0] = av.x; a[i][1] = av.y; a[i][2] = av.z; a[i][3] = av.w;
            }
            #pragma unroll
            for (int j = 0; j < 4; j++) {
                ulonglong2 bp = *(const ulonglong2*)&Bs[buf][k4 + j][tx << 2];
                #pragma unroll
                for (int i = 0; i < 4; i++) {
                    unsigned long long aa = pack2(a[i][j], a[i][j]);
                    ffma2(acc2[i][0], aa, bp.x);
                    ffma2(acc2[i][1], aa, bp.y);
                }
            }
        }
        __syncthreads();   // compute done before next issue overwrites buf^1
    }

    #pragma unroll
    for (int i = 0; i < 4; i++) {
        float2 f01 = unpack2(acc2[i][0]);
        float2 f23 = unpack2(acc2[i][1]);
        float4 v = make_float4(f01.x, f01.y, f23.x, f23.y);
        *(float4*)(C + (size_t)(row0 + (ty << 2) + i) * NE + (tx << 2)) = v;
    }
}

// ---------------------------------------------------------------------------
// Kernel B: scores + exp + row-reciprocal.  MUFU(tanh)-bound.
// Block = (b, 8 t-rows), 256 threads; warp w owns t=t0+w; lane owns q=ch*32+lane.
// q tiles (32 rows x 128) double-buffered via cp.async (unpadded rows).
// Compute uses rotated index e2=(e+lane)&127 -> conflict-free unpadded reads.
// p[b,t,q] = exp(sum_e vc[e]*tanh(k[t,e]+q[q,e]))  (no max pass; |sjt| <= ~9)
// ---------------------------------------------------------------------------
__global__ __launch_bounds__(256) void score_kernel(const float* __restrict__ vc)
{
    __shared__ float ks[8][128];
    __shared__ float qs[2][32][128];   // unpadded: 16B-aligned rows for cp.async
    __shared__ float vcs[128];

    const int b   = blockIdx.y;
    const int t0  = blockIdx.x << 3;
    const int tid = threadIdx.x;
    const int w    = tid >> 5;
    const int lane = tid & 31;

    {   // k tile [8 x 128]
        int lin = tid << 2;
        int r = lin >> 7, c = lin & 127;
        *(float4*)&ks[r][c] =
            *(const float4*)(g_kproj + (size_t)(b * NTK + t0 + r) * NE + c);
    }
    if (tid < 128) vcs[tid] = vc[tid];

    const float* qb = g_qproj + (size_t)b * NTQ * NE;

    auto issue_chunk = [&](int ch, int buf) {
        #pragma unroll
        for (int i = 0; i < 4; i++) {      // 4 x 16B chunks/thread
            int c  = tid + (i << 8);
            int r  = c >> 5;
            int j4 = (c & 31) << 2;
            cp16(smem_u32(&qs[buf][r][j4]),
                 qb + (size_t)(ch * 32 + r) * NE + j4);
        }
        cp_commit();
    };

    issue_chunk(0, 0);

    const int t = t0 + w;
    float* __restrict__ prow = g_p + ((size_t)b * NTK + t) * NTQ;
    float zsum = 0.f;

    for (int ch = 0; ch < 16; ch++) {
        const int buf = ch & 1;
        if (ch < 15) { issue_chunk(ch + 1, buf ^ 1); cp_wait<1>(); }
        else         { cp_wait<0>(); }
        __syncthreads();               // q chunk + (iter0: ks/vcs) visible

        const float* __restrict__ kr = ks[w];
        const float* __restrict__ q0 = qs[buf][lane];
        float acc0 = 0.f;
        #pragma unroll 16
        for (int e = 0; e < 128; e++) {
            int e2 = (e + lane) & 127; // rotated: conflict-free, deterministic
            acc0 += vcs[e2] * tanh_fast(kr[e2] + q0[e2]);
        }

        float p0 = __expf(acc0);
        prow[ch * 32 + lane] = p0;
        zsum += p0;
        __syncthreads();               // done with buf before it is refilled
    }

    #pragma unroll
    for (int off = 16; off; off >>= 1)
        zsum += __shfl_xor_sync(0xffffffffu, zsum, off);
    if (lane == 0) g_zr[b * NTK + t] = 1.0f / zsum;
}

// ---------------------------------------------------------------------------
// Kernel C: out[b,d,q] = sum_t (value[b,d,t] * zr[b,t]) * p[b,t,q]
// SGEMM M=256, N=512, K=512 per batch; tile 32x64, 128 threads, 4x4 micro,
// f32x2 math, cp.async double buffer.  zr folded into B rows in-loop (f32x2).
// ---------------------------------------------------------------------------
__global__ __launch_bounds__(128) void out_kernel(
    const float* __restrict__ value, float* __restrict__ out)
{
    __shared__ float As[2][32][32];    // [buf][m][k]  4KB/buf
    __shared__ float Bs[2][32][64];    // [buf][k][n]  8KB/buf
    __shared__ float zrs[NTK];

    const int b   = blockIdx.z;
    const int n0  = blockIdx.x << 6;
    const int m0  = blockIdx.y << 5;
    const int tid = threadIdx.x;
    const int tx  = tid & 15;          // 16 over N (x4 cols)
    const int ty  = tid >> 4;          // 8 over M  (x4 rows)

    #pragma unroll
    for (int i = 0; i < 4; i++)
        zrs[tid + (i << 7)] = g_zr[b * NTK + tid + (i << 7)];

    const float* Av = value + (size_t)b * NF * NTK;
    const float* Bp = g_p   + (size_t)b * NTK * NTQ;

    auto issue_stage = [&](int kk, int buf) {
        #pragma unroll
        for (int i = 0; i < 2; i++) {      // A: 2 chunks/thread
            int c  = tid + (i << 7);
            int m  = c >> 3;
            int kc = (c & 7) << 2;
            cp16(smem_u32(&As[buf][m][kc]),
                 Av + (size_t)(m0 + m) * NTK + kk + kc);
        }
        #pragma unroll
        for (int i = 0; i < 4; i++) {      // B: 4 chunks/thread
            int c  = tid + (i << 7);
            int k  = c >> 4;
            int n4 = (c & 15) << 2;
            cp16(smem_u32(&Bs[buf][k][n4]),
                 Bp + (size_t)(kk + k) * NTQ + n0 + n4);
        }
        cp_commit();
    };

    issue_stage(0, 0);

    unsigned long long acc2[4][2];
    #pragma unroll
    for (int i = 0; i < 4; i++) { acc2[i][0] = 0ULL; acc2[i][1] = 0ULL; }

    for (int it = 0; it < 16; it++) {
        const int buf = it & 1;
        const int kk  = it << 5;
        if (it < 15) { issue_stage(kk + 32, buf ^ 1); cp_wait<1>(); }
        else         { cp_wait<0>(); }
        __syncthreads();               // stage data + (iter0: zrs) visible

        #pragma unroll
        for (int k4 = 0; k4 < 32; k4 += 4) {
            float a[4][4];
            #pragma unroll
            for (int i = 0; i < 4; i++) {
                float4 av = *(const float4*)&As[buf][(ty << 2) + i][k4];  // bcast
                a[i][0] = av.x; a[i][1] = av.y; a[i][2] = av.z; a[i][3] = av.w;
            }
            float4 z4 = *(const float4*)&zrs[kk + k4];                    // bcast
            float zk[4] = {z4.x, z4.y, z4.z, z4.w};
            #pragma unroll
            for (int j = 0; j < 4; j++) {
                ulonglong2 bp = *(const ulonglong2*)&Bs[buf][k4 + j][tx << 2];
                unsigned long long zz = pack2(zk[j], zk[j]);
                unsigned long long b0 = mul2(bp.x, zz);   // fold 1/Z into B row
                unsigned long long b1 = mul2(bp.y, zz);
                #pragma unroll
                for (int i = 0; i < 4; i++) {
                    unsigned long long aa = pack2(a[i][j], a[i][j]);
                    ffma2(acc2[i][0], aa, b0);
                    ffma2(acc2[i][1], aa, b1);
                }
            }
        }
        __syncthreads();
    }

    #pragma unroll
    for (int i = 0; i < 4; i++) {
        float2 f01 = unpack2(acc2[i][0]);
        float2 f23 = unpack2(acc2[i][1]);
        float4 v = make_float4(f01.x, f01.y, f23.x, f23.y);
        *(float4*)(out + (size_t)(b * NF + m0 + (ty << 2) + i) * NTQ + n0 + (tx << 2)) = v;
    }
}

// ---------------------------------------------------------------------------
extern "C" void kernel_launch(void* const* d_in, const int* in_sizes, int n_in,
                              void* d_out, int out_size)
{
    const float* query = (const float*)d_in[0];
    const float* key   = (const float*)d_in[1];
    const float* value = (const float*)d_in[2];
    const float* W1    = (const float*)d_in[3];
    const float* W2    = (const float*)d_in[4];
    const float* vc    = (const float*)d_in[5];
    float* out = (float*)d_out;

    proj_kernel <<<dim3(128, 2), 128>>>(query, key, W1, W2);  // 2048/16 rows x {q,k}
    score_kernel<<<dim3(64, 4), 256>>>(vc);                   // TK/8 x B
    out_kernel  <<<dim3(8, 8, 4), 128>>>(value, out);         // N/64 x M/32 x B
}

// round 8
// speedup vs baseline: 1.2091x; 1.2091x over previous
#include <cuda_runtime.h>
#include <cstdint>

#define NB  4
#define NTQ 512
#define NTK 512
#define NE  128
#define NF  256   // TWO_E

// Scratch (no allocations allowed)
__device__ float g_qproj[NB * NTQ * NE];               // 1 MB
__device__ float g_kproj[NB * NTK * NE];               // 1 MB
__device__ float g_p[(size_t)NB * NTK * NTQ];          // 4 MB (unnormalized exp)
__device__ float g_zr[NB * NTK];                       // 1/rowsum per (b,t)

__device__ __forceinline__ float tanh_fast(float x) {
    float y;
    asm("tanh.approx.f32 %0, %1;" : "=f"(y) : "f"(x));
    return y;
}

// ---- packed fp32x2 helpers (FFMA2/FMUL2; bit-exact IEEE fp32 per lane) ----
__device__ __forceinline__ unsigned long long pack2(float x, float y) {
    unsigned long long r;
    asm("mov.b64 %0, {%1, %2};" : "=l"(r) : "f"(x), "f"(y));
    return r;
}
__device__ __forceinline__ void ffma2(unsigned long long& d,
                                      unsigned long long a, unsigned long long b) {
    asm("fma.rn.f32x2 %0, %1, %2, %0;" : "+l"(d) : "l"(a), "l"(b));
}
__device__ __forceinline__ unsigned long long mul2(unsigned long long a,
                                                   unsigned long long b) {
    unsigned long long r;
    asm("mul.rn.f32x2 %0, %1, %2;" : "=l"(r) : "l"(a), "l"(b));
    return r;
}
__device__ __forceinline__ float2 unpack2(unsigned long long v) {
    float2 f;
    asm("mov.b64 {%0, %1}, %2;" : "=f"(f.x), "=f"(f.y) : "l"(v));
    return f;
}

// ---- cp.async helpers ----
__device__ __forceinline__ uint32_t smem_u32(const void* p) {
    return (uint32_t)__cvta_generic_to_shared(p);
}
__device__ __forceinline__ void cp16(uint32_t dst, const void* src) {
    asm volatile("cp.async.ca.shared.global [%0], [%1], 16;"
                 :: "r"(dst), "l"(src) : "memory");
}
__device__ __forceinline__ void cp_commit() {
    asm volatile("cp.async.commit_group;" ::: "memory");
}
template <int N>
__device__ __forceinline__ void cp_wait() {
    asm volatile("cp.async.wait_group %0;" :: "n"(N) : "memory");
}

// ---------------------------------------------------------------------------
// Kernel A: projections.  C[r,e] = sum_f A[r,f] * W[f,e]
// A: [2048 x 256], W: [256 x 128].  blockIdx.y selects (query,W1) / (key,W2).
// Tile 16x128, stage K=32, 128 threads, 4x4 micro-tile, f32x2 math.
// 2-buffer cp.async pipeline, ONE __syncthreads per iter:
//   iter it: wait<0> (stage it landed) -> sync -> issue stage it+1 into buf^1
//            -> compute buf.  Safe: buf^1's readers were iter it-1, all past
//   this barrier.  smem = 2*(2KB+16KB) = 36KB (fits 48KB static limit).
// ---------------------------------------------------------------------------
__global__ __launch_bounds__(128) void proj_kernel(
    const float* __restrict__ query, const float* __restrict__ key,
    const float* __restrict__ W1, const float* __restrict__ W2)
{
    const float* A; const float* W; float* C;
    if (blockIdx.y == 0) { A = query; W = W1; C = g_qproj; }
    else                 { A = key;   W = W2; C = g_kproj; }

    __shared__ float As[2][16][32];    // [buf][m][k]  2KB/buf
    __shared__ float Bs[2][32][128];   // [buf][k][n] 16KB/buf

    const int tid = threadIdx.x;
    const int tx = tid & 31;           // 32 threads over N (x4 cols)
    const int ty = tid >> 5;           // 4 threads over M  (x4 rows)
    const int row0 = blockIdx.x * 16;

    // cp.async chunk mapping (16B chunks)
    const int a_r  = tid >> 3;             // A: 1 chunk/thread
    const int a_c  = (tid & 7) << 2;
    const float* a_src = A + (size_t)(row0 + a_r) * NF + a_c;

    auto issue_stage = [&](int st) {       // stage index 0..7, buf = st&1
        const int buf = st & 1;
        const int kk  = st << 5;
        cp16(smem_u32(&As[buf][a_r][a_c]), a_src + kk);
        #pragma unroll
        for (int i = 0; i < 8; i++) {      // B: 8 chunks/thread
            int c  = tid + (i << 7);
            int k  = c >> 5;
            int n4 = (c & 31) << 2;
            cp16(smem_u32(&Bs[buf][k][n4]), W + (size_t)(kk + k) * NE + n4);
        }
        cp_commit();
    };

    issue_stage(0);

    unsigned long long acc2[4][2];
    #pragma unroll
    for (int i = 0; i < 4; i++) { acc2[i][0] = 0ULL; acc2[i][1] = 0ULL; }

    #pragma unroll
    for (int it = 0; it < 8; it++) {
        const int buf = it & 1;
        cp_wait<0>();                  // stage it landed
        __syncthreads();               // publishes it; retires readers of buf^1
        if (it < 7) issue_stage(it + 1);

        #pragma unroll
        for (int k4 = 0; k4 < 32; k4 += 4) {
            float a[4][4];
            #pragma unroll
            for (int i = 0; i < 4; i++) {
                float4 av = *(const float4*)&As[buf][(ty << 2) + i][k4];  // bcast
                a[i][0] = av.x; a[i][1] = av.y; a[i][2] = av.z; a[i][3] = av.w;
            }
            #pragma unroll
            for (int j = 0; j < 4; j++) {
                ulonglong2 bp = *(const ulonglong2*)&Bs[buf][k4 + j][tx << 2];
                #pragma unroll
                for (int i = 0; i < 4; i++) {
                    unsigned long long aa = pack2(a[i][j], a[i][j]);
                    ffma2(acc2[i][0], aa, bp.x);
                    ffma2(acc2[i][1], aa, bp.y);
                }
            }
        }
    }

    #pragma unroll
    for (int i = 0; i < 4; i++) {
        float2 f01 = unpack2(acc2[i][0]);
        float2 f23 = unpack2(acc2[i][1]);
        float4 v = make_float4(f01.x, f01.y, f23.x, f23.y);
        *(float4*)(C + (size_t)(row0 + (ty << 2) + i) * NE + (tx << 2)) = v;
    }
}

// ---------------------------------------------------------------------------
// Kernel B: scores + exp + row-reciprocal.  MUFU(tanh)-bound (at floor).
// R5 form: padded smem, register prefetch, CONSTANT-index compute loop
// (immediate-offset LDS keeps per-e issue cost under the MUFU budget).
// p[b,t,q] = exp(sum_e vc[e]*tanh(k[t,e]+q[q,e]))  (no max pass; |sjt| <= ~9)
// ---------------------------------------------------------------------------
__global__ __launch_bounds__(256) void score_kernel(const float* __restrict__ vc)
{
    __shared__ float ks[8][128];
    __shared__ float qs[2][32][129];   // +1 pad: lane-per-row reads conflict-free
    __shared__ float vcs[128];

    const int b   = blockIdx.y;
    const int t0  = blockIdx.x << 3;
    const int tid = threadIdx.x;
    const int w    = tid >> 5;
    const int lane = tid & 31;

    {   // k tile [8 x 128]
        int lin = tid << 2;
        int r = lin >> 7, c = lin & 127;
        *(float4*)&ks[r][c] =
            *(const float4*)(g_kproj + (size_t)(b * NTK + t0 + r) * NE + c);
    }
    if (tid < 128) vcs[tid] = vc[tid];

    // q chunk load mapping: thread covers column c0, rows rbase, rbase+2, ...
    const int c0    = tid & 127;
    const int rbase = tid >> 7;        // 0 or 1
    const float* qbase = g_qproj + (size_t)b * NTQ * NE + rbase * NE + c0;

    float pref[16];
    #pragma unroll
    for (int i = 0; i < 16; i++)       // chunk 0
        pref[i] = qbase[(size_t)(2 * i) * NE];
    #pragma unroll
    for (int i = 0; i < 16; i++)
        qs[0][rbase + 2 * i][c0] = pref[i];
    __syncthreads();

    const int t = t0 + w;
    float* __restrict__ prow = g_p + ((size_t)b * NTK + t) * NTQ;
    float zsum = 0.f;

    for (int ch = 0; ch < 16; ch++) {
        const int buf = ch & 1;
        if (ch < 15) {                 // prefetch next 32-q chunk (overlaps tanh loop)
            const float* src = qbase + (size_t)(ch + 1) * 32 * NE;
            #pragma unroll
            for (int i = 0; i < 16; i++)
                pref[i] = src[(size_t)(2 * i) * NE];
        }

        const float* __restrict__ kr = ks[w];          // warp broadcast
        const float* __restrict__ q0 = qs[buf][lane];
        float acc0 = 0.f;
        #pragma unroll 16
        for (int e = 0; e < 128; e++)
            acc0 += vcs[e] * tanh_fast(kr[e] + q0[e]);

        float p0 = __expf(acc0);
        prow[ch * 32 + lane] = p0;
        zsum += p0;

        if (ch < 15) {
            __syncthreads();           // all warps done with buf^1 (chunk ch-1)
            #pragma unroll
            for (int i = 0; i < 16; i++)
                qs[buf ^ 1][rbase + 2 * i][c0] = pref[i];
            __syncthreads();
        }
    }

    #pragma unroll
    for (int off = 16; off; off >>= 1)
        zsum += __shfl_xor_sync(0xffffffffu, zsum, off);
    if (lane == 0) g_zr[b * NTK + t] = 1.0f / zsum;
}

// ---------------------------------------------------------------------------
// Kernel C: out[b,d,q] = sum_t (value[b,d,t] * zr[b,t]) * p[b,t,q]
// SGEMM M=256, N=512, K=512 per batch; tile 32x64, 128 threads, 4x4 micro,
// f32x2 math.  3-stage cp.async pipeline, ONE sync per iter:
//   iter it: wait<1> -> sync -> issue stage it+2 into buf (it-1)%3 -> compute.
// smem = 3*(4KB+8KB) + 2KB = 38KB.  zr folded into B rows in-loop via mul2.
// ---------------------------------------------------------------------------
__global__ __launch_bounds__(128) void out_kernel(
    const float* __restrict__ value, float* __restrict__ out)
{
    __shared__ float As[3][32][32];    // [buf][m][k]  4KB/buf
    __shared__ float Bs[3][32][64];    // [buf][k][n]  8KB/buf
    __shared__ float zrs[NTK];

    const int b   = blockIdx.z;
    const int n0  = blockIdx.x << 6;
    const int m0  = blockIdx.y << 5;
    const int tid = threadIdx.x;
    const int tx  = tid & 15;          // 16 over N (x4 cols)
    const int ty  = tid >> 4;          // 8 over M  (x4 rows)

    #pragma unroll
    for (int i = 0; i < 4; i++)
        zrs[tid + (i << 7)] = g_zr[b * NTK + tid + (i << 7)];

    const float* Av = value + (size_t)b * NF * NTK;
    const float* Bp = g_p   + (size_t)b * NTK * NTQ;

    auto issue_stage = [&](int st) {       // stage 0..15, buf = st%3
        const int buf = st % 3;
        const int kk  = st << 5;
        #pragma unroll
        for (int i = 0; i < 2; i++) {      // A: 2 chunks/thread
            int c  = tid + (i << 7);
            int m  = c >> 3;
            int kc = (c & 7) << 2;
            cp16(smem_u32(&As[buf][m][kc]),
                 Av + (size_t)(m0 + m) * NTK + kk + kc);
        }
        #pragma unroll
        for (int i = 0; i < 4; i++) {      // B: 4 chunks/thread
            int c  = tid + (i << 7);
            int k  = c >> 4;
            int n4 = (c & 15) << 2;
            cp16(smem_u32(&Bs[buf][k][n4]),
                 Bp + (size_t)(kk + k) * NTQ + n0 + n4);
        }
        cp_commit();
    };

    issue_stage(0);
    issue_stage(1);

    unsigned long long acc2[4][2];
    #pragma unroll
    for (int i = 0; i < 4; i++) { acc2[i][0] = 0ULL; acc2[i][1] = 0ULL; }

    #pragma unroll
    for (int it = 0; it < 16; it++) {
        const int buf = it % 3;
        const int kk  = it << 5;
        if (it < 15) cp_wait<1>(); else cp_wait<0>();
        __syncthreads();               // publishes stage it; also zrs on it=0
        if (it < 14) issue_stage(it + 2);

        #pragma unroll
        for (int k4 = 0; k4 < 32; k4 += 4) {
            float a[4][4];
            #pragma unroll
            for (int i = 0; i < 4; i++) {
                float4 av = *(const float4*)&As[buf][(ty << 2) + i][k4];  // bcast
                a[i][0] = av.x; a[i][1] = av.y; a[i][2] = av.z; a[i][3] = av.w;
            }
            float4 z4 = *(const float4*)&zrs[kk + k4];                    // bcast
            float zk[4] = {z4.x, z4.y, z4.z, z4.w};
            #pragma unroll
            for (int j = 0; j < 4; j++) {
                ulonglong2 bp = *(const ulonglong2*)&Bs[buf][k4 + j][tx << 2];
                unsigned long long zz = pack2(zk[j], zk[j]);
                unsigned long long b0 = mul2(bp.x, zz);   // fold 1/Z into B row
                unsigned long long b1 = mul2(bp.y, zz);
                #pragma unroll
                for (int i = 0; i < 4; i++) {
                    unsigned long long aa = pack2(a[i][j], a[i][j]);
                    ffma2(acc2[i][0], aa, b0);
                    ffma2(acc2[i][1], aa, b1);
                }
            }
        }
    }

    #pragma unroll
    for (int i = 0; i < 4; i++) {
        float2 f01 = unpack2(acc2[i][0]);
        float2 f23 = unpack2(acc2[i][1]);
        float4 v = make_float4(f01.x, f01.y, f23.x, f23.y);
        *(float4*)(out + (size_t)(b * NF + m0 + (ty << 2) + i) * NTQ + n0 + (tx << 2)) = v;
    }
}

// ---------------------------------------------------------------------------
extern "C" void kernel_launch(void* const* d_in, const int* in_sizes, int n_in,
                              void* d_out, int out_size)
{
    const float* query = (const float*)d_in[0];
    const float* key   = (const float*)d_in[1];
    const float* value = (const float*)d_in[2];
    const float* W1    = (const float*)d_in[3];
    const float* W2    = (const float*)d_in[4];
    const float* vc    = (const float*)d_in[5];
    float* out = (float*)d_out;

    proj_kernel <<<dim3(128, 2), 128>>>(query, key, W1, W2);  // 2048/16 rows x {q,k}
    score_kernel<<<dim3(64, 4), 256>>>(vc);                   // TK/8 x B
    out_kernel  <<<dim3(8, 8, 4), 128>>>(value, out);         // N/64 x M/32 x B
}